// round 11
// baseline (speedup 1.0000x reference)
#include <cuda_runtime.h>

// DPLoss: masked per-row MSE of (pred - log(alignment)), normalized by row
// length, then mean over batch.
//
// Inputs (metadata order):
//   d_in[0] = pred            float32 [B, T]
//   d_in[1] = alignment       float32 [B, T]
//   d_in[2] = token_lengths   int32   [B]
// Output: scalar float32.
//
// Design (R11 = R10 re-bench after infra failure): dynamic work-stealing.
// R9 was tail-bound (static chunk assignment -> slowest block ~2x mean,
// DRAM diluted to 32% although bytes moved equaled the useful minimum).
// Each 256-thread block pulls whole-row tickets from a global atomic
// counter: imbalance bounded by one row (~0.2us). Single launch; fused
// last-block epilogue resets ticket/slots/counter for graph replay.
// Ticket smem slot is double-buffered by iteration parity to need only one
// barrier per row.

#define BLOCK_THREADS 256
#define NSLOTS 64
#define GRID_BLOCKS 1184          // 8 per SM target on 148 SMs

__device__ float        g_slots[NSLOTS];   // zero-init at module load
__device__ unsigned int g_counter;         // zero-init at module load
__device__ unsigned int g_ticket;          // zero-init at module load

__global__ __launch_bounds__(BLOCK_THREADS) void dploss_steal(
    const float* __restrict__ pred,
    const float* __restrict__ alignment,
    const int*   __restrict__ lens,
    float* __restrict__ out,
    int T, int B, float inv_B, unsigned int nblocks)
{
    float acc = 0.0f;               // running, scaled by inv_B/len per row

    __shared__ unsigned int s_row[2];   // parity double-buffer

    int parity = 0;
    for (;; parity ^= 1) {
        if (threadIdx.x == 0)
            s_row[parity] = atomicAdd(&g_ticket, 1u);
        __syncthreads();
        const unsigned int row = s_row[parity];
        if (row >= (unsigned int)B) break;

        const int len  = __ldg(lens + row);
        const int nvec = (len + 3) >> 2;

        const float4* __restrict__ p4 =
            reinterpret_cast<const float4*>(pred + (size_t)row * T);
        const float4* __restrict__ a4 =
            reinterpret_cast<const float4*>(alignment + (size_t)row * T);

        const int v0 = threadIdx.x;
        const int v1 = v0 + BLOCK_THREADS;
        const bool m0 = v0 < nvec;
        const bool m1 = v1 < nvec;

        // Front-load all global reads (up to 4 LDG.128 in flight / thread).
        float4 p0, a0, p1, a1;
        if (m0) { p0 = p4[v0]; a0 = a4[v0]; }
        if (m1) { p1 = p4[v1]; a1 = a4[v1]; }

        float cs = 0.0f;            // this row's per-thread partial (unscaled)

        if (m0) {
            const int base = v0 << 2;
            if (base + 4 <= len) {
                float d0 = p0.x - __logf(a0.x);
                float d1 = p0.y - __logf(a0.y);
                float d2 = p0.z - __logf(a0.z);
                float d3 = p0.w - __logf(a0.w);
                cs = fmaf(d0, d0, cs);
                cs = fmaf(d1, d1, cs);
                cs = fmaf(d2, d2, cs);
                cs = fmaf(d3, d3, cs);
            } else {
                if (base + 0 < len) { float d = p0.x - __logf(a0.x); cs = fmaf(d, d, cs); }
                if (base + 1 < len) { float d = p0.y - __logf(a0.y); cs = fmaf(d, d, cs); }
                if (base + 2 < len) { float d = p0.z - __logf(a0.z); cs = fmaf(d, d, cs); }
                if (base + 3 < len) { float d = p0.w - __logf(a0.w); cs = fmaf(d, d, cs); }
            }
        }
        if (m1) {
            const int base = v1 << 2;
            if (base + 4 <= len) {
                float d0 = p1.x - __logf(a1.x);
                float d1 = p1.y - __logf(a1.y);
                float d2 = p1.z - __logf(a1.z);
                float d3 = p1.w - __logf(a1.w);
                cs = fmaf(d0, d0, cs);
                cs = fmaf(d1, d1, cs);
                cs = fmaf(d2, d2, cs);
                cs = fmaf(d3, d3, cs);
            } else {
                if (base + 0 < len) { float d = p1.x - __logf(a1.x); cs = fmaf(d, d, cs); }
                if (base + 1 < len) { float d = p1.y - __logf(a1.y); cs = fmaf(d, d, cs); }
                if (base + 2 < len) { float d = p1.z - __logf(a1.z); cs = fmaf(d, d, cs); }
                if (base + 3 < len) { float d = p1.w - __logf(a1.w); cs = fmaf(d, d, cs); }
            }
        }

        acc = fmaf(cs, inv_B / (float)len, acc);   // exact by linearity
    }

    // ---- one block reduction + one scatter atomic per block ----
    #pragma unroll
    for (int off = 16; off > 0; off >>= 1)
        acc += __shfl_xor_sync(0xFFFFFFFFu, acc, off);

    __shared__ float warp_sums[8];
    const int wid = threadIdx.x >> 5;
    const int lid = threadIdx.x & 31;
    if (lid == 0) warp_sums[wid] = acc;
    __syncthreads();

    if (threadIdx.x == 0) {
        float s = 0.0f;
        #pragma unroll
        for (int w = 0; w < BLOCK_THREADS / 32; w++) s += warp_sums[w];
        atomicAdd(&g_slots[blockIdx.x & (NSLOTS - 1)], s);
        __threadfence();                 // slot write visible before arrival
    }
    __syncthreads();

    __shared__ unsigned int s_prev;
    if (threadIdx.x == 0)
        s_prev = atomicAdd(&g_counter, 1u);
    __syncthreads();

    if (s_prev == nblocks - 1u) {
        // Last block: fold slots -> scalar, reset device state for replay.
        __threadfence();

        float v = (threadIdx.x < NSLOTS) ? g_slots[threadIdx.x] : 0.0f;
        #pragma unroll
        for (int off = 16; off > 0; off >>= 1)
            v += __shfl_xor_sync(0xFFFFFFFFu, v, off);

        __shared__ float ws[2];
        if (wid < 2 && lid == 0) ws[wid] = v;
        __syncthreads();

        if (threadIdx.x == 0) {
            out[0] = ws[0] + ws[1];
            g_counter = 0u;
            g_ticket  = 0u;
        }
        if (threadIdx.x < NSLOTS)
            g_slots[threadIdx.x] = 0.0f;
    }
}

extern "C" void kernel_launch(void* const* d_in, const int* in_sizes, int n_in,
                              void* d_out, int out_size)
{
    const float* pred      = (const float*)d_in[0];
    const float* alignment = (const float*)d_in[1];
    const int*   lens      = (const int*)d_in[2];
    float*       out       = (float*)d_out;

    const int B = in_sizes[2];
    const int T = in_sizes[0] / B;

    int nblocks = GRID_BLOCKS;
    if (nblocks > B) nblocks = B;

    dploss_steal<<<nblocks, BLOCK_THREADS>>>(
        pred, alignment, lens, out, T, B, 1.0f / (float)B,
        (unsigned int)nblocks);
}